// round 16
// baseline (speedup 1.0000x reference)
#include <cuda_runtime.h>
#include <mma.h>
#include <math.h>

using namespace nvcuda;

// Problem constants
constexpr int NB   = 2;
constexpr int NH   = 16;
constexpr int SEQ  = 2048;
constexpr int HD   = 128;
constexpr int HIDN = 2048;   // NH*HD
constexpr int QKVN = 6144;   // 3*HIDN

// Scratch (static device memory; allocation APIs are forbidden).
// RULE (r15 post-mortem): these symbols are ONLY referenced inside device
// code. Passing their address from host code yields the host shadow symbol
// and silently corrupts the run.
__device__ float g_q[(size_t)NB * NH * SEQ * HD];
__device__ float g_k[(size_t)NB * NH * SEQ * HD];
__device__ float g_v[(size_t)NB * NH * SEQ * HD];
__device__ float g_ctx[(size_t)NB * SEQ * HIDN];
__device__ float g_hid[(size_t)NB * SEQ * HIDN];     // tf32-rounded hidden
__device__ float g_wqkv[(size_t)HIDN * QKVN];        // tf32-rounded W_qkv [k][n]
__device__ float g_wd[(size_t)HIDN * HIDN];          // tf32-rounded W_dense [k][n]

__device__ __forceinline__ float tf32r(float x) { return wmma::__float_to_tf32(x); }

__device__ __forceinline__ void cp_async16(void* dst, const void* src) {
    unsigned s = (unsigned)__cvta_generic_to_shared(dst);
    asm volatile("cp.async.cg.shared.global [%0], [%1], 16;" :: "r"(s), "l"(src));
}

__device__ __forceinline__ void mma_tf32_16x8x8(float* d, const unsigned* a,
                                                unsigned b0, unsigned b1)
{
    asm volatile(
        "mma.sync.aligned.m16n8k8.row.col.f32.tf32.tf32.f32 "
        "{%0,%1,%2,%3}, {%4,%5,%6,%7}, {%8,%9}, {%0,%1,%2,%3};\n"
        : "+f"(d[0]), "+f"(d[1]), "+f"(d[2]), "+f"(d[3])
        : "r"(a[0]), "r"(a[1]), "r"(a[2]), "r"(a[3]), "r"(b0), "r"(b1));
}

// ---------------------------------------------------------------------------
// Pre-pass: round inputs to tf32. Three template-selected kernels, each
// naming its destination __device__ symbol in DEVICE code (host passes only
// harness input pointers). Split so gemm0 becomes launch #4 (ncu target).
// ---------------------------------------------------------------------------
constexpr int N4_HID = (NB * SEQ * HIDN) / 4;     // 2097152
constexpr int N4_WQ  = (HIDN * QKVN) / 4;         // 3145728
constexpr int N4_WD  = (HIDN * HIDN) / 4;         // 1048576

template <int WHICH>
__global__ void __launch_bounds__(256) round_pre(const float4* __restrict__ src)
{
    int i = blockIdx.x * 256 + threadIdx.x;
    float4* dst = (WHICH == 0) ? (float4*)g_hid
                : (WHICH == 1) ? (float4*)g_wqkv
                               : (float4*)g_wd;
    float4 v = src[i];
    v.x = tf32r(v.x); v.y = tf32r(v.y); v.z = tf32r(v.z); v.w = tf32r(v.w);
    dst[i] = v;
}

// ---------------------------------------------------------------------------
// Raw-mma tf32 GEMM, block 128x128, k-tile 32.
// 4 warps (128 threads) in 2x2 grid, warp tile 64x64 = 4x8 m16n8k8 accums
// (validated round-14 core). 3-stage cp.async ring, single barrier per
// k-tile (r11-validated schedule; r15's failure was the host-symbol bug,
// not this schedule) -> 2 k-tiles of load cover.
// smem 3 x 35328 B = 105984 B -> 2 CTA/SM at 128 threads.
// MODE 0: g_hid @ g_wqkv -> scatter tf32-rounded to g_q/g_k/g_v [B,H,S,D].
// MODE 1: g_ctx @ g_wd -> Cout (fp32, final output).
// ---------------------------------------------------------------------------
constexpr int ASZ = 128 * 36;            // A stage floats
constexpr int BSZ = 32 * 132;            // B stage floats
constexpr int GEMM_SMEM = 3 * (ASZ + BSZ) * 4;   // 105984 B -> 2 CTA/SM

template <int MODE>
__global__ void __launch_bounds__(128, 2) gemm_raw(float* __restrict__ Cout)
{
    constexpr int N     = (MODE == 0) ? QKVN : HIDN;
    constexpr int NUM_N = N / 128;
    constexpr int GM    = 8;
    constexpr int KT    = HIDN / 32;     // 64

    extern __shared__ __align__(16) float sm[];
    float* As = sm;                      // 3 stages of ASZ
    float* Bs = sm + 3 * ASZ;            // 3 stages of BSZ

    const int tid  = threadIdx.x;
    const int wid  = tid >> 5;
    const int lane = tid & 31;
    const int g    = lane >> 2;
    const int t    = lane & 3;
    const int wm   = wid >> 1;           // 0..1  (64 m-rows each)
    const int wn   = wid & 1;            // 0..1  (64 n-cols each)

    const int bid   = blockIdx.x;
    const int perg  = GM * NUM_N;
    const int grp   = bid / perg;
    const int rem   = bid - grp * perg;
    const int n_idx = rem / GM;
    const int m_idx = grp * GM + (rem - n_idx * GM);
    const int m0 = m_idx * 128;
    const int n0 = n_idx * 128;

    const float* Ap = (MODE == 0) ? g_hid : g_ctx;
    const float* Bw = (MODE == 0) ? g_wqkv : g_wd;

    float acc[4][8][4];
#pragma unroll
    for (int i = 0; i < 4; i++)
#pragma unroll
        for (int j = 0; j < 8; j++)
#pragma unroll
            for (int e = 0; e < 4; e++) acc[i][j][e] = 0.0f;

    auto issue = [&](int kt, int st) {
        int k0 = kt * 32;
        // A: 128x32 floats = 1024 float4, 128 threads -> 8 iters
#pragma unroll
        for (int it = 0; it < 8; it++) {
            int idx = tid + it * 128;
            int r = idx >> 3, c = (idx & 7) * 4;
            cp_async16(&As[st * ASZ + r * 36 + c], &Ap[(size_t)(m0 + r) * HIDN + k0 + c]);
        }
        // B: 32x128 floats = 1024 float4
#pragma unroll
        for (int it = 0; it < 8; it++) {
            int idx = tid + it * 128;
            int r = idx >> 5, c = (idx & 31) * 4;
            cp_async16(&Bs[st * BSZ + r * 132 + c], &Bw[(size_t)(k0 + r) * N + n0 + c]);
        }
        asm volatile("cp.async.commit_group;");
    };

    // prologue: 2 stages in flight; stage 0 complete before first compute
    issue(0, 0);
    issue(1, 1);
    asm volatile("cp.async.wait_group 1;");
    __syncthreads();

    for (int kt = 0; kt < KT; kt++) {
        // writes target buffer (kt+2)%3 == (kt-1)%3: its reads finished before
        // the barrier that ended iteration kt-1 -> safe (r11-validated).
        if (kt + 2 < KT) issue(kt + 2, (kt + 2) % 3);

        const float* Ab = &As[(kt % 3) * ASZ];
        const float* Bb = &Bs[(kt % 3) * BSZ];

#pragma unroll
        for (int ks = 0; ks < 4; ks++) {
            // A fragments: 4 m-tiles (conflict-free pattern, validated)
            unsigned a[4][4];
#pragma unroll
            for (int mi = 0; mi < 4; mi++) {
                const float* ab = Ab + (wm * 64 + mi * 16) * 36 + ks * 8;
                a[mi][0] = __float_as_uint(ab[g * 36 + t]);
                a[mi][1] = __float_as_uint(ab[(g + 8) * 36 + t]);
                a[mi][2] = __float_as_uint(ab[g * 36 + t + 4]);
                a[mi][3] = __float_as_uint(ab[(g + 8) * 36 + t + 4]);
            }
            // B fragments: 8 n-tiles (validated pattern, stride 132)
            unsigned bf[8][2];
#pragma unroll
            for (int ni = 0; ni < 8; ni++) {
                int col = wn * 64 + ni * 8 + g;
                bf[ni][0] = __float_as_uint(Bb[(ks * 8 + t) * 132 + col]);
                bf[ni][1] = __float_as_uint(Bb[(ks * 8 + t + 4) * 132 + col]);
            }
            // 32 independent MMAs
#pragma unroll
            for (int mi = 0; mi < 4; mi++)
#pragma unroll
                for (int ni = 0; ni < 8; ni++)
                    mma_tf32_16x8x8(acc[mi][ni], a[mi], bf[ni][0], bf[ni][1]);
        }

        if (kt + 1 < KT) {
            // ensure next compute stage (kt+1) is complete, then one barrier
            if (kt + 2 < KT) asm volatile("cp.async.wait_group 1;");
            else             asm volatile("cp.async.wait_group 0;");
            __syncthreads();
        }
    }

    // ---- epilogue: C layout c0(g,2t) c1(g,2t+1) c2(g+8,2t) c3(g+8,2t+1) ----
    if (MODE == 0) {
        int head = n_idx / 3;
        int typ  = n_idx % 3;
        int bb   = m0 >> 11;
        int s0   = m0 & (SEQ - 1);
        float* basep = (typ == 0 ? g_q : (typ == 1 ? g_k : g_v)) +
                       ((size_t)(bb * NH + head) * SEQ + s0) * HD;
#pragma unroll
        for (int mi = 0; mi < 4; mi++) {
            int r0 = wm * 64 + mi * 16 + g;
#pragma unroll
            for (int ni = 0; ni < 8; ni++) {
                int c = wn * 64 + ni * 8 + 2 * t;
                float2 v0 = make_float2(tf32r(acc[mi][ni][0]), tf32r(acc[mi][ni][1]));
                float2 v1 = make_float2(tf32r(acc[mi][ni][2]), tf32r(acc[mi][ni][3]));
                *(float2*)&basep[(size_t)r0 * HD + c]       = v0;
                *(float2*)&basep[(size_t)(r0 + 8) * HD + c] = v1;
            }
        }
    } else {
#pragma unroll
        for (int mi = 0; mi < 4; mi++) {
            int r0 = m0 + wm * 64 + mi * 16 + g;
#pragma unroll
            for (int ni = 0; ni < 8; ni++) {
                int c = n0 + wn * 64 + ni * 8 + 2 * t;
                float2 v0 = make_float2(acc[mi][ni][0], acc[mi][ni][1]);
                float2 v1 = make_float2(acc[mi][ni][2], acc[mi][ni][3]);
                *(float2*)&Cout[(size_t)r0 * HIDN + c]       = v0;
                *(float2*)&Cout[(size_t)(r0 + 8) * HIDN + c] = v1;
            }
        }
    }
}

// ---------------------------------------------------------------------------
// xpos RoPE on first 32 dims of q and k; outputs tf32-rounded.
// ---------------------------------------------------------------------------
__global__ void __launch_bounds__(256) rope_kernel()
{
    int idx = blockIdx.x * 256 + threadIdx.x;
    int j  = idx & 15;
    int s  = (idx >> 4) & (SEQ - 1);
    int bh = idx >> 15;
    size_t base = ((size_t)bh * SEQ + s) * HD;

    double invf = exp(-(double)j / 16.0 * 9.210340371976184);
    double f = (double)s * invf;
    double sn, c;
    sincos(f, &sn, &c);
    double scj = (2.0 * j + 0.4 * 32.0) / (1.4 * 32.0);
    double pw  = ((double)s - 1024.0) / 512.0;
    double sc  = pow(scj, pw);

    float cq = (float)(c * sc),  sq = (float)(sn * sc);
    float ck = (float)(c / sc),  sk = (float)(sn / sc);

    float a = g_q[base + j], b = g_q[base + j + 16];
    g_q[base + j]      = tf32r(a * cq - b * sq);
    g_q[base + j + 16] = tf32r(b * cq + a * sq);

    a = g_k[base + j]; b = g_k[base + j + 16];
    g_k[base + j]      = tf32r(a * ck - b * sk);
    g_k[base + j + 16] = tf32r(b * ck + a * sk);
}

// ---------------------------------------------------------------------------
// Flash attention v3 (validated, 387us): 128-row q-tile, 8 warps, register O,
// cp.async double-buffered K/V, raw mma m16n8k8 tf32.
// ---------------------------------------------------------------------------
constexpr int KVS = 64 * 132;   // one K or V stage, floats

__global__ void __launch_bounds__(256, 1) flash_attn3(const float* __restrict__ amask)
{
    extern __shared__ __align__(16) float fsm[];

    const int tid  = threadIdx.x;
    const int wid  = tid >> 5;
    const int lane = tid & 31;
    const int g    = lane >> 2;
    const int t    = lane & 3;
    const int qt   = gridDim.x - 1 - blockIdx.x;
    const int h    = blockIdx.y;
    const int b    = blockIdx.z;
    const int bh   = b * NH + h;
    const int wr   = wid * 16;

    const float scale = 0.08838834764831845f;
    const float* am = amask + (size_t)b * SEQ;

    const float* qg = g_q + ((size_t)bh * SEQ + qt * 128) * HD;
    for (int idx = tid; idx < 128 * 32; idx += 256) {
        int r = idx >> 5, c = (idx & 31) * 4;
        cp_async16(&fsm[r * 132 + c], &qg[r * HD + c]);
    }
    asm volatile("cp.async.commit_group;");
    asm volatile("cp.async.wait_group 0;");
    __syncthreads();

    unsigned qa[16][4];
#pragma unroll
    for (int kc = 0; kc < 16; kc++) {
        qa[kc][0] = __float_as_uint(fsm[(wr + g)     * 132 + kc * 8 + t]);
        qa[kc][1] = __float_as_uint(fsm[(wr + g + 8) * 132 + kc * 8 + t]);
        qa[kc][2] = __float_as_uint(fsm[(wr + g)     * 132 + kc * 8 + t + 4]);
        qa[kc][3] = __float_as_uint(fsm[(wr + g + 8) * 132 + kc * 8 + t + 4]);
    }
    __syncthreads();

    float o[16][4];
#pragma unroll
    for (int i = 0; i < 16; i++)
#pragma unroll
        for (int j = 0; j < 4; j++) o[i][j] = 0.0f;
    float m0 = -3.0e38f, m1 = -3.0e38f, l0 = 0.0f, l1 = 0.0f;

    const int qp0 = qt * 128 + wr + g;
    const int qp1 = qp0 + 8;
    const int srcA = (lane & 28) | (t >> 1);
    const int srcB = srcA + 2;

    const float* kg0 = g_k + ((size_t)bh * SEQ) * HD;
    const float* vg0 = g_v + ((size_t)bh * SEQ) * HD;

    auto issue = [&](int kt, int st) {
        const float* kg = kg0 + (size_t)kt * 64 * HD;
        const float* vg = vg0 + (size_t)kt * 64 * HD;
        float* Kd = fsm + st * KVS;
        float* Vd = fsm + 2 * KVS + st * KVS;
        for (int idx = tid; idx < 64 * 32; idx += 256) {
            int r = idx >> 5, c = (idx & 31) * 4;
            cp_async16(&Kd[r * 132 + c], &kg[r * HD + c]);
            cp_async16(&Vd[r * 132 + c], &vg[r * HD + c]);
        }
        asm volatile("cp.async.commit_group;");
    };

    const int nk = 2 * qt + 2;
    issue(0, 0);

    for (int kt = 0; kt < nk; kt++) {
        if (kt + 1 < nk) {
            issue(kt + 1, (kt + 1) & 1);
            asm volatile("cp.async.wait_group 1;");
        } else {
            asm volatile("cp.async.wait_group 0;");
        }
        __syncthreads();

        const float* Ks = fsm + (kt & 1) * KVS;
        const float* Vs = fsm + 2 * KVS + (kt & 1) * KVS;

        float sacc[8][4];
#pragma unroll
        for (int nt = 0; nt < 8; nt++)
#pragma unroll
            for (int e = 0; e < 4; e++) sacc[nt][e] = 0.0f;
#pragma unroll
        for (int kc = 0; kc < 16; kc++) {
#pragma unroll
            for (int nt = 0; nt < 8; nt++) {
                unsigned b0 = __float_as_uint(Ks[(nt * 8 + g) * 132 + kc * 8 + t]);
                unsigned b1 = __float_as_uint(Ks[(nt * 8 + g) * 132 + kc * 8 + t + 4]);
                mma_tf32_16x8x8(sacc[nt], qa[kc], b0, b1);
            }
        }

        const bool needm = (kt * 64 + 63 > qt * 128 + wr);
        float mx0 = -3.0e38f, mx1 = -3.0e38f;
#pragma unroll
        for (int nt = 0; nt < 8; nt++) {
            int col = kt * 64 + nt * 8 + 2 * t;
            float a0 = am[col], a1 = am[col + 1];
            float s0 = sacc[nt][0] * scale + a0;
            float s1 = sacc[nt][1] * scale + a1;
            float s2 = sacc[nt][2] * scale + a0;
            float s3 = sacc[nt][3] * scale + a1;
            if (needm) {
                if (col     > qp0) s0 = -1.0e30f;
                if (col + 1 > qp0) s1 = -1.0e30f;
                if (col     > qp1) s2 = -1.0e30f;
                if (col + 1 > qp1) s3 = -1.0e30f;
            }
            sacc[nt][0] = s0; sacc[nt][1] = s1; sacc[nt][2] = s2; sacc[nt][3] = s3;
            mx0 = fmaxf(mx0, fmaxf(s0, s1));
            mx1 = fmaxf(mx1, fmaxf(s2, s3));
        }
        mx0 = fmaxf(mx0, __shfl_xor_sync(0xffffffffu, mx0, 1));
        mx0 = fmaxf(mx0, __shfl_xor_sync(0xffffffffu, mx0, 2));
        mx1 = fmaxf(mx1, __shfl_xor_sync(0xffffffffu, mx1, 1));
        mx1 = fmaxf(mx1, __shfl_xor_sync(0xffffffffu, mx1, 2));

        float mn0 = fmaxf(m0, mx0), mn1 = fmaxf(m1, mx1);
        float al0 = __expf(m0 - mn0), al1 = __expf(m1 - mn1);
        m0 = mn0; m1 = mn1;

        float ps0 = 0.0f, ps1 = 0.0f;
#pragma unroll
        for (int nt = 0; nt < 8; nt++) {
            float p0 = __expf(sacc[nt][0] - mn0);
            float p1 = __expf(sacc[nt][1] - mn0);
            float p2 = __expf(sacc[nt][2] - mn1);
            float p3 = __expf(sacc[nt][3] - mn1);
            sacc[nt][0] = p0; sacc[nt][1] = p1; sacc[nt][2] = p2; sacc[nt][3] = p3;
            ps0 += p0 + p1;
            ps1 += p2 + p3;
        }
        ps0 += __shfl_xor_sync(0xffffffffu, ps0, 1);
        ps0 += __shfl_xor_sync(0xffffffffu, ps0, 2);
        ps1 += __shfl_xor_sync(0xffffffffu, ps1, 1);
        ps1 += __shfl_xor_sync(0xffffffffu, ps1, 2);
        l0 = l0 * al0 + ps0;
        l1 = l1 * al1 + ps1;

#pragma unroll
        for (int i = 0; i < 16; i++) {
            o[i][0] *= al0; o[i][1] *= al0;
            o[i][2] *= al1; o[i][3] *= al1;
        }

#pragma unroll
        for (int kc = 0; kc < 8; kc++) {
            unsigned p0 = __float_as_uint(tf32r(sacc[kc][0]));
            unsigned p1 = __float_as_uint(tf32r(sacc[kc][1]));
            unsigned p2 = __float_as_uint(tf32r(sacc[kc][2]));
            unsigned p3 = __float_as_uint(tf32r(sacc[kc][3]));
            unsigned x0 = __shfl_sync(0xffffffffu, p0, srcA);
            unsigned x1 = __shfl_sync(0xffffffffu, p1, srcA);
            unsigned y0 = __shfl_sync(0xffffffffu, p2, srcA);
            unsigned y1 = __shfl_sync(0xffffffffu, p3, srcA);
            unsigned z0 = __shfl_sync(0xffffffffu, p0, srcB);
            unsigned z1 = __shfl_sync(0xffffffffu, p1, srcB);
            unsigned w0 = __shfl_sync(0xffffffffu, p2, srcB);
            unsigned w1 = __shfl_sync(0xffffffffu, p3, srcB);
            unsigned pa[4];
            pa[0] = (t & 1) ? x1 : x0;
            pa[1] = (t & 1) ? y1 : y0;
            pa[2] = (t & 1) ? z1 : z0;
            pa[3] = (t & 1) ? w1 : w0;
#pragma unroll
            for (int nt = 0; nt < 16; nt++) {
                unsigned b0 = __float_as_uint(Vs[(kc * 8 + t)     * 132 + nt * 8 + g]);
                unsigned b1 = __float_as_uint(Vs[(kc * 8 + t + 4) * 132 + nt * 8 + g]);
                mma_tf32_16x8x8(o[nt], pa, b0, b1);
            }
        }
        __syncthreads();
    }

    float inv0 = 1.0f / l0, inv1 = 1.0f / l1;
    float* outp = g_ctx + ((size_t)(b * SEQ + qt * 128 + wr)) * HIDN + h * HD;
#pragma unroll
    for (int nt = 0; nt < 16; nt++) {
        float2 v0 = make_float2(tf32r(o[nt][0] * inv0), tf32r(o[nt][1] * inv0));
        float2 v1 = make_float2(tf32r(o[nt][2] * inv1), tf32r(o[nt][3] * inv1));
        *(float2*)&outp[(size_t)g * HIDN + nt * 8 + 2 * t]       = v0;
        *(float2*)&outp[(size_t)(g + 8) * HIDN + nt * 8 + 2 * t] = v1;
    }
}

// ---------------------------------------------------------------------------
// Launch (prepass = 3 launches so gemm0 is launch #4 -> ncu target; each
// prepass kernel receives ONLY harness input pointers, destinations are
// resolved inside device code)
// ---------------------------------------------------------------------------
extern "C" void kernel_launch(void* const* d_in, const int* in_sizes, int n_in,
                              void* d_out, int out_size)
{
    const float* hidden = (const float*)d_in[0];
    const float* amask  = (const float*)d_in[1];
    const float* wqkv   = (const float*)d_in[2];
    const float* wdense = (const float*)d_in[3];
    float* out = (float*)d_out;

    constexpr int FLASH_SMEM = 4 * KVS * 4;   // 135168 B

    cudaFuncSetAttribute((const void*)gemm_raw<0>,
                         cudaFuncAttributeMaxDynamicSharedMemorySize, GEMM_SMEM);
    cudaFuncSetAttribute((const void*)gemm_raw<1>,
                         cudaFuncAttributeMaxDynamicSharedMemorySize, GEMM_SMEM);
    cudaFuncSetAttribute((const void*)flash_attn3,
                         cudaFuncAttributeMaxDynamicSharedMemorySize, FLASH_SMEM);

    // 0) pre-pass (3 launches): round hidden / W_qkv / W_dense to tf32
    round_pre<0><<<N4_HID / 256, 256>>>((const float4*)hidden);
    round_pre<1><<<N4_WQ / 256, 256>>>((const float4*)wqkv);
    round_pre<2><<<N4_WD / 256, 256>>>((const float4*)wdense);
    // 1) QKV projection -> g_q/g_k/g_v [B,H,S,D]  (launch #4: ncu target)
    gemm_raw<0><<<32 * 48, 128, GEMM_SMEM>>>(nullptr);
    // 2) xpos rotary on first 32 dims of q,k
    rope_kernel<<<(NB * NH * SEQ * 16) / 256, 256>>>();
    // 3) causal flash attention -> g_ctx
    flash_attn3<<<dim3(SEQ / 128, NH, NB), 256, FLASH_SMEM>>>(amask);
    // 4) output projection -> d_out
    gemm_raw<1><<<32 * 16, 128, GEMM_SMEM>>>(out);
}

// round 17
// speedup vs baseline: 1.1073x; 1.1073x over previous
#include <cuda_runtime.h>
#include <mma.h>
#include <math.h>
#include <stdint.h>

using namespace nvcuda;

// Problem constants
constexpr int NB   = 2;
constexpr int NH   = 16;
constexpr int SEQ  = 2048;
constexpr int HD   = 128;
constexpr int HIDN = 2048;   // NH*HD
constexpr int QKVN = 6144;   // 3*HIDN

// Scratch (static device memory; allocation APIs are forbidden).
// RULE (r15): these symbols are ONLY referenced inside device code.
__device__ float g_q[(size_t)NB * NH * SEQ * HD];
__device__ float g_k[(size_t)NB * NH * SEQ * HD];
__device__ float g_v[(size_t)NB * NH * SEQ * HD];
__device__ float g_ctx[(size_t)NB * SEQ * HIDN];
__device__ float g_hid[(size_t)NB * SEQ * HIDN];     // tf32-rounded hidden
__device__ float g_wqkvT[(size_t)QKVN * HIDN];       // tf32-rounded W_qkv^T [n][k]
__device__ float g_wdT[(size_t)HIDN * HIDN];         // tf32-rounded W_dense^T [n][k]

__device__ __forceinline__ float tf32r(float x) { return wmma::__float_to_tf32(x); }

__device__ __forceinline__ void cp_async16(void* dst, const void* src) {
    unsigned s = (unsigned)__cvta_generic_to_shared(dst);
    asm volatile("cp.async.cg.shared.global [%0], [%1], 16;" :: "r"(s), "l"(src));
}

// SW128 swizzle on byte offsets within 128B-row tiles
#define SWZ(off) ((off) ^ (((off) >> 3) & 0x70))

__device__ __forceinline__ void ldsm4(unsigned* r, uint32_t addr) {
    asm volatile("ldmatrix.sync.aligned.m8n8.x4.shared.b16 {%0,%1,%2,%3}, [%4];"
                 : "=r"(r[0]), "=r"(r[1]), "=r"(r[2]), "=r"(r[3]) : "r"(addr));
}

__device__ __forceinline__ void mma_tf32_16x8x8(float* d, const unsigned* a,
                                                unsigned b0, unsigned b1)
{
    asm volatile(
        "mma.sync.aligned.m16n8k8.row.col.f32.tf32.tf32.f32 "
        "{%0,%1,%2,%3}, {%4,%5,%6,%7}, {%8,%9}, {%0,%1,%2,%3};\n"
        : "+f"(d[0]), "+f"(d[1]), "+f"(d[2]), "+f"(d[3])
        : "r"(a[0]), "r"(a[1]), "r"(a[2]), "r"(a[3]), "r"(b0), "r"(b1));
}

// ---------------------------------------------------------------------------
// Pre-pass: round hidden; transpose+round weights to [n][k].
// Destinations resolved in DEVICE code (r15 rule). 3 launches -> gemm0 = #4.
// ---------------------------------------------------------------------------
constexpr int N4_HID = (NB * SEQ * HIDN) / 4;     // 2097152

__global__ void __launch_bounds__(256) round_hid_pre(const float4* __restrict__ src)
{
    int i = blockIdx.x * 256 + threadIdx.x;
    float4 v = src[i];
    v.x = tf32r(v.x); v.y = tf32r(v.y); v.z = tf32r(v.z); v.w = tf32r(v.w);
    ((float4*)g_hid)[i] = v;
}

template <int WHICH>   // 0: W_qkv -> g_wqkvT, 1: W_dense -> g_wdT
__global__ void __launch_bounds__(256) transpose_pre(const float* __restrict__ src)
{
    constexpr int K = HIDN;
    constexpr int N = (WHICH == 0) ? QKVN : HIDN;
    float* dst = (WHICH == 0) ? g_wqkvT : g_wdT;   // device-resolved
    __shared__ float tsm[32][33];
    int n0 = blockIdx.x * 32, k0 = blockIdx.y * 32;
    int tx = threadIdx.x, ty = threadIdx.y;
#pragma unroll
    for (int i = ty; i < 32; i += 8)
        tsm[i][tx] = src[(size_t)(k0 + i) * N + n0 + tx];
    __syncthreads();
#pragma unroll
    for (int i = ty; i < 32; i += 8)
        dst[(size_t)(n0 + i) * K + k0 + tx] = tf32r(tsm[tx][i]);
}

// ---------------------------------------------------------------------------
// Raw-mma tf32 GEMM with ldmatrix fragment loads.
// Block 128x128, k-tile 32, 3-stage cp.async ring (single barrier/k-tile,
// r16-validated). 4 warps in 2x2, warp tile 64x64 = 4x8 m16n8k8 accums.
// Both operands K-major 128B rows (A [m][k], B [n][k]) with SW128 swizzle.
// Per warp per k8-step: 4 A-LDSM.x4 + 4 B-LDSM.x4 (8 instrs) + 32 HMMA,
// replacing 32 scalar LDS -> attacks the measured L1=45%/issue co-limit.
// ldmatrix x4 mapping (b16 m8n8): matrix j <- addrs of lanes 8j..8j+7;
// result reg j of lane l = matrix j [row l>>2][float col l&3].
//   A: mat0 rows+0..7 chk0 = a0, mat1 rows+8..15 chk0 = a1,
//      mat2 rows+0..7 chk1 = a2, mat3 rows+8..15 chk1 = a3.
//   B: mat0 n+0..7 chk0 = b0(ntile 2p), mat1 n+0..7 chk1 = b1(ntile 2p),
//      mat2 n+8..15 chk0 = b0(ntile 2p+1), mat3 chk1 = b1(ntile 2p+1).
// MODE 0: g_hid @ g_wqkvT^T -> scatter tf32-rounded to g_q/g_k/g_v.
// MODE 1: g_ctx @ g_wdT^T -> Cout.
// ---------------------------------------------------------------------------
constexpr int STG_B = 32768;                     // bytes/stage: A 16KB + B 16KB
constexpr int GEMM_SMEM = 3 * STG_B;             // 98304 B -> 2 CTA/SM (reg-capped)

template <int MODE>
__global__ void __launch_bounds__(128, 2) gemm_raw(float* __restrict__ Cout)
{
    constexpr int N     = (MODE == 0) ? QKVN : HIDN;
    constexpr int NUM_N = N / 128;
    constexpr int GM    = 8;
    constexpr int KT    = HIDN / 32;     // 64

    extern __shared__ __align__(16) char smc[];
    const uint32_t sb = (uint32_t)__cvta_generic_to_shared(smc);

    const int tid  = threadIdx.x;
    const int wid  = tid >> 5;
    const int lane = tid & 31;
    const int g    = lane >> 2;
    const int t    = lane & 3;
    const int wm   = wid >> 1;           // 0..1
    const int wn   = wid & 1;            // 0..1

    const int bid   = blockIdx.x;
    const int perg  = GM * NUM_N;
    const int grp   = bid / perg;
    const int rem   = bid - grp * perg;
    const int n_idx = rem / GM;
    const int m_idx = grp * GM + (rem - n_idx * GM);
    const int m0 = m_idx * 128;
    const int n0 = n_idx * 128;

    const float* Ap = (MODE == 0) ? g_hid : g_ctx;
    const float* Bt = (MODE == 0) ? g_wqkvT : g_wdT;

    float acc[4][8][4];
#pragma unroll
    for (int i = 0; i < 4; i++)
#pragma unroll
        for (int j = 0; j < 8; j++)
#pragma unroll
            for (int e = 0; e < 4; e++) acc[i][j][e] = 0.0f;

    auto issue = [&](int kt, int st) {
        int k0 = kt * 32;
        char* base = smc + st * STG_B;
        // A: 128 rows x 8 chunks of 16B, 128 threads -> 8 iters
#pragma unroll
        for (int it = 0; it < 8; it++) {
            int idx = tid + it * 128;
            int r = idx >> 3, c = idx & 7;
            cp_async16(base + SWZ((uint32_t)(r * 128 + c * 16)),
                       Ap + (size_t)(m0 + r) * HIDN + k0 + c * 4);
        }
        // B: 128 n-rows x 8 chunks of 16B from Bt[n][k]
#pragma unroll
        for (int it = 0; it < 8; it++) {
            int idx = tid + it * 128;
            int r = idx >> 3, c = idx & 7;
            cp_async16(base + 16384 + SWZ((uint32_t)(r * 128 + c * 16)),
                       Bt + (size_t)(n0 + r) * HIDN + k0 + c * 4);
        }
        asm volatile("cp.async.commit_group;");
    };

    // ldmatrix per-lane row/chunk selectors
    const int asel = lane >> 3;                       // 0..3
    const int arow = (asel & 1) * 8 + (lane & 7);     // A: mat0/2 rows 0-7, mat1/3 rows 8-15
    const int achk = asel >> 1;                       // A: mat0/1 chk0, mat2/3 chk1
    const int brow = (asel >> 1) * 8 + (lane & 7);    // B: mat0/1 rows 0-7, mat2/3 rows 8-15
    const int bchk = asel & 1;                        // B: mat0/2 chk0, mat1/3 chk1

    // prologue: 2 stages in flight; stage 0 complete before first compute
    issue(0, 0);
    issue(1, 1);
    asm volatile("cp.async.wait_group 1;");
    __syncthreads();

    for (int kt = 0; kt < KT; kt++) {
        if (kt + 2 < KT) issue(kt + 2, (kt + 2) % 3);

        uint32_t abase = sb + (kt % 3) * STG_B;
        uint32_t bbase = abase + 16384;

#pragma unroll
        for (int ks = 0; ks < 4; ks++) {
            unsigned a[4][4];
#pragma unroll
            for (int mi = 0; mi < 4; mi++) {
                int row = wm * 64 + mi * 16 + arow;
                ldsm4(a[mi], abase + SWZ((uint32_t)(row * 128 + (ks * 2 + achk) * 16)));
            }
            unsigned bp[4][4];
#pragma unroll
            for (int p = 0; p < 4; p++) {
                int row = wn * 64 + p * 16 + brow;
                ldsm4(bp[p], bbase + SWZ((uint32_t)(row * 128 + (ks * 2 + bchk) * 16)));
            }
#pragma unroll
            for (int mi = 0; mi < 4; mi++)
#pragma unroll
                for (int ni = 0; ni < 8; ni++)
                    mma_tf32_16x8x8(acc[mi][ni], a[mi],
                                    bp[ni >> 1][(ni & 1) * 2],
                                    bp[ni >> 1][(ni & 1) * 2 + 1]);
        }

        if (kt + 1 < KT) {
            if (kt + 2 < KT) asm volatile("cp.async.wait_group 1;");
            else             asm volatile("cp.async.wait_group 0;");
            __syncthreads();
        }
    }

    // ---- epilogue: C layout c0(g,2t) c1(g,2t+1) c2(g+8,2t) c3(g+8,2t+1) ----
    if (MODE == 0) {
        int head = n_idx / 3;
        int typ  = n_idx % 3;
        int bb   = m0 >> 11;
        int s0   = m0 & (SEQ - 1);
        float* basep = (typ == 0 ? g_q : (typ == 1 ? g_k : g_v)) +
                       ((size_t)(bb * NH + head) * SEQ + s0) * HD;
#pragma unroll
        for (int mi = 0; mi < 4; mi++) {
            int r0 = wm * 64 + mi * 16 + g;
#pragma unroll
            for (int ni = 0; ni < 8; ni++) {
                int c = wn * 64 + ni * 8 + 2 * t;
                float2 v0 = make_float2(tf32r(acc[mi][ni][0]), tf32r(acc[mi][ni][1]));
                float2 v1 = make_float2(tf32r(acc[mi][ni][2]), tf32r(acc[mi][ni][3]));
                *(float2*)&basep[(size_t)r0 * HD + c]       = v0;
                *(float2*)&basep[(size_t)(r0 + 8) * HD + c] = v1;
            }
        }
    } else {
#pragma unroll
        for (int mi = 0; mi < 4; mi++) {
            int r0 = m0 + wm * 64 + mi * 16 + g;
#pragma unroll
            for (int ni = 0; ni < 8; ni++) {
                int c = n0 + wn * 64 + ni * 8 + 2 * t;
                float2 v0 = make_float2(acc[mi][ni][0], acc[mi][ni][1]);
                float2 v1 = make_float2(acc[mi][ni][2], acc[mi][ni][3]);
                *(float2*)&Cout[(size_t)r0 * HIDN + c]       = v0;
                *(float2*)&Cout[(size_t)(r0 + 8) * HIDN + c] = v1;
            }
        }
    }
}

// ---------------------------------------------------------------------------
// xpos RoPE on first 32 dims of q and k; outputs tf32-rounded.
// ---------------------------------------------------------------------------
__global__ void __launch_bounds__(256) rope_kernel()
{
    int idx = blockIdx.x * 256 + threadIdx.x;
    int j  = idx & 15;
    int s  = (idx >> 4) & (SEQ - 1);
    int bh = idx >> 15;
    size_t base = ((size_t)bh * SEQ + s) * HD;

    double invf = exp(-(double)j / 16.0 * 9.210340371976184);
    double f = (double)s * invf;
    double sn, c;
    sincos(f, &sn, &c);
    double scj = (2.0 * j + 0.4 * 32.0) / (1.4 * 32.0);
    double pw  = ((double)s - 1024.0) / 512.0;
    double sc  = pow(scj, pw);

    float cq = (float)(c * sc),  sq = (float)(sn * sc);
    float ck = (float)(c / sc),  sk = (float)(sn / sc);

    float a = g_q[base + j], b = g_q[base + j + 16];
    g_q[base + j]      = tf32r(a * cq - b * sq);
    g_q[base + j + 16] = tf32r(b * cq + a * sq);

    a = g_k[base + j]; b = g_k[base + j + 16];
    g_k[base + j]      = tf32r(a * ck - b * sk);
    g_k[base + j + 16] = tf32r(b * ck + a * sk);
}

// ---------------------------------------------------------------------------
// Flash attention v3 (validated, 387us): 128-row q-tile, 8 warps, register O,
// cp.async double-buffered K/V, raw mma m16n8k8 tf32.
// ---------------------------------------------------------------------------
constexpr int KVS = 64 * 132;   // one K or V stage, floats

__global__ void __launch_bounds__(256, 1) flash_attn3(const float* __restrict__ amask)
{
    extern __shared__ __align__(16) float fsm[];

    const int tid  = threadIdx.x;
    const int wid  = tid >> 5;
    const int lane = tid & 31;
    const int g    = lane >> 2;
    const int t    = lane & 3;
    const int qt   = gridDim.x - 1 - blockIdx.x;
    const int h    = blockIdx.y;
    const int b    = blockIdx.z;
    const int bh   = b * NH + h;
    const int wr   = wid * 16;

    const float scale = 0.08838834764831845f;
    const float* am = amask + (size_t)b * SEQ;

    const float* qg = g_q + ((size_t)bh * SEQ + qt * 128) * HD;
    for (int idx = tid; idx < 128 * 32; idx += 256) {
        int r = idx >> 5, c = (idx & 31) * 4;
        cp_async16(&fsm[r * 132 + c], &qg[r * HD + c]);
    }
    asm volatile("cp.async.commit_group;");
    asm volatile("cp.async.wait_group 0;");
    __syncthreads();

    unsigned qa[16][4];
#pragma unroll
    for (int kc = 0; kc < 16; kc++) {
        qa[kc][0] = __float_as_uint(fsm[(wr + g)     * 132 + kc * 8 + t]);
        qa[kc][1] = __float_as_uint(fsm[(wr + g + 8) * 132 + kc * 8 + t]);
        qa[kc][2] = __float_as_uint(fsm[(wr + g)     * 132 + kc * 8 + t + 4]);
        qa[kc][3] = __float_as_uint(fsm[(wr + g + 8) * 132 + kc * 8 + t + 4]);
    }
    __syncthreads();

    float o[16][4];
#pragma unroll
    for (int i = 0; i < 16; i++)
#pragma unroll
        for (int j = 0; j < 4; j++) o[i][j] = 0.0f;
    float m0 = -3.0e38f, m1 = -3.0e38f, l0 = 0.0f, l1 = 0.0f;

    const int qp0 = qt * 128 + wr + g;
    const int qp1 = qp0 + 8;
    const int srcA = (lane & 28) | (t >> 1);
    const int srcB = srcA + 2;

    const float* kg0 = g_k + ((size_t)bh * SEQ) * HD;
    const float* vg0 = g_v + ((size_t)bh * SEQ) * HD;

    auto issue = [&](int kt, int st) {
        const float* kg = kg0 + (size_t)kt * 64 * HD;
        const float* vg = vg0 + (size_t)kt * 64 * HD;
        float* Kd = fsm + st * KVS;
        float* Vd = fsm + 2 * KVS + st * KVS;
        for (int idx = tid; idx < 64 * 32; idx += 256) {
            int r = idx >> 5, c = (idx & 31) * 4;
            cp_async16(&Kd[r * 132 + c], &kg[r * HD + c]);
            cp_async16(&Vd[r * 132 + c], &vg[r * HD + c]);
        }
        asm volatile("cp.async.commit_group;");
    };

    const int nk = 2 * qt + 2;
    issue(0, 0);

    for (int kt = 0; kt < nk; kt++) {
        if (kt + 1 < nk) {
            issue(kt + 1, (kt + 1) & 1);
            asm volatile("cp.async.wait_group 1;");
        } else {
            asm volatile("cp.async.wait_group 0;");
        }
        __syncthreads();

        const float* Ks = fsm + (kt & 1) * KVS;
        const float* Vs = fsm + 2 * KVS + (kt & 1) * KVS;

        float sacc[8][4];
#pragma unroll
        for (int nt = 0; nt < 8; nt++)
#pragma unroll
            for (int e = 0; e < 4; e++) sacc[nt][e] = 0.0f;
#pragma unroll
        for (int kc = 0; kc < 16; kc++) {
#pragma unroll
            for (int nt = 0; nt < 8; nt++) {
                unsigned b0 = __float_as_uint(Ks[(nt * 8 + g) * 132 + kc * 8 + t]);
                unsigned b1 = __float_as_uint(Ks[(nt * 8 + g) * 132 + kc * 8 + t + 4]);
                mma_tf32_16x8x8(sacc[nt], qa[kc], b0, b1);
            }
        }

        const bool needm = (kt * 64 + 63 > qt * 128 + wr);
        float mx0 = -3.0e38f, mx1 = -3.0e38f;
#pragma unroll
        for (int nt = 0; nt < 8; nt++) {
            int col = kt * 64 + nt * 8 + 2 * t;
            float a0 = am[col], a1 = am[col + 1];
            float s0 = sacc[nt][0] * scale + a0;
            float s1 = sacc[nt][1] * scale + a1;
            float s2 = sacc[nt][2] * scale + a0;
            float s3 = sacc[nt][3] * scale + a1;
            if (needm) {
                if (col     > qp0) s0 = -1.0e30f;
                if (col + 1 > qp0) s1 = -1.0e30f;
                if (col     > qp1) s2 = -1.0e30f;
                if (col + 1 > qp1) s3 = -1.0e30f;
            }
            sacc[nt][0] = s0; sacc[nt][1] = s1; sacc[nt][2] = s2; sacc[nt][3] = s3;
            mx0 = fmaxf(mx0, fmaxf(s0, s1));
            mx1 = fmaxf(mx1, fmaxf(s2, s3));
        }
        mx0 = fmaxf(mx0, __shfl_xor_sync(0xffffffffu, mx0, 1));
        mx0 = fmaxf(mx0, __shfl_xor_sync(0xffffffffu, mx0, 2));
        mx1 = fmaxf(mx1, __shfl_xor_sync(0xffffffffu, mx1, 1));
        mx1 = fmaxf(mx1, __shfl_xor_sync(0xffffffffu, mx1, 2));

        float mn0 = fmaxf(m0, mx0), mn1 = fmaxf(m1, mx1);
        float al0 = __expf(m0 - mn0), al1 = __expf(m1 - mn1);
        m0 = mn0; m1 = mn1;

        float ps0 = 0.0f, ps1 = 0.0f;
#pragma unroll
        for (int nt = 0; nt < 8; nt++) {
            float p0 = __expf(sacc[nt][0] - mn0);
            float p1 = __expf(sacc[nt][1] - mn0);
            float p2 = __expf(sacc[nt][2] - mn1);
            float p3 = __expf(sacc[nt][3] - mn1);
            sacc[nt][0] = p0; sacc[nt][1] = p1; sacc[nt][2] = p2; sacc[nt][3] = p3;
            ps0 += p0 + p1;
            ps1 += p2 + p3;
        }
        ps0 += __shfl_xor_sync(0xffffffffu, ps0, 1);
        ps0 += __shfl_xor_sync(0xffffffffu, ps0, 2);
        ps1 += __shfl_xor_sync(0xffffffffu, ps1, 1);
        ps1 += __shfl_xor_sync(0xffffffffu, ps1, 2);
        l0 = l0 * al0 + ps0;
        l1 = l1 * al1 + ps1;

#pragma unroll
        for (int i = 0; i < 16; i++) {
            o[i][0] *= al0; o[i][1] *= al0;
            o[i][2] *= al1; o[i][3] *= al1;
        }

#pragma unroll
        for (int kc = 0; kc < 8; kc++) {
            unsigned p0 = __float_as_uint(tf32r(sacc[kc][0]));
            unsigned p1 = __float_as_uint(tf32r(sacc[kc][1]));
            unsigned p2 = __float_as_uint(tf32r(sacc[kc][2]));
            unsigned p3 = __float_as_uint(tf32r(sacc[kc][3]));
            unsigned x0 = __shfl_sync(0xffffffffu, p0, srcA);
            unsigned x1 = __shfl_sync(0xffffffffu, p1, srcA);
            unsigned y0 = __shfl_sync(0xffffffffu, p2, srcA);
            unsigned y1 = __shfl_sync(0xffffffffu, p3, srcA);
            unsigned z0 = __shfl_sync(0xffffffffu, p0, srcB);
            unsigned z1 = __shfl_sync(0xffffffffu, p1, srcB);
            unsigned w0 = __shfl_sync(0xffffffffu, p2, srcB);
            unsigned w1 = __shfl_sync(0xffffffffu, p3, srcB);
            unsigned pa[4];
            pa[0] = (t & 1) ? x1 : x0;
            pa[1] = (t & 1) ? y1 : y0;
            pa[2] = (t & 1) ? z1 : z0;
            pa[3] = (t & 1) ? w1 : w0;
#pragma unroll
            for (int nt = 0; nt < 16; nt++) {
                unsigned b0 = __float_as_uint(Vs[(kc * 8 + t)     * 132 + nt * 8 + g]);
                unsigned b1 = __float_as_uint(Vs[(kc * 8 + t + 4) * 132 + nt * 8 + g]);
                mma_tf32_16x8x8(o[nt], pa, b0, b1);
            }
        }
        __syncthreads();
    }

    float inv0 = 1.0f / l0, inv1 = 1.0f / l1;
    float* outp = g_ctx + ((size_t)(b * SEQ + qt * 128 + wr)) * HIDN + h * HD;
#pragma unroll
    for (int nt = 0; nt < 16; nt++) {
        float2 v0 = make_float2(tf32r(o[nt][0] * inv0), tf32r(o[nt][1] * inv0));
        float2 v1 = make_float2(tf32r(o[nt][2] * inv1), tf32r(o[nt][3] * inv1));
        *(float2*)&outp[(size_t)g * HIDN + nt * 8 + 2 * t]       = v0;
        *(float2*)&outp[(size_t)(g + 8) * HIDN + nt * 8 + 2 * t] = v1;
    }
}

// ---------------------------------------------------------------------------
// Launch (3 prepass launches -> gemm0 is launch #4, the ncu target)
// ---------------------------------------------------------------------------
extern "C" void kernel_launch(void* const* d_in, const int* in_sizes, int n_in,
                              void* d_out, int out_size)
{
    const float* hidden = (const float*)d_in[0];
    const float* amask  = (const float*)d_in[1];
    const float* wqkv   = (const float*)d_in[2];
    const float* wdense = (const float*)d_in[3];
    float* out = (float*)d_out;

    constexpr int FLASH_SMEM = 4 * KVS * 4;   // 135168 B

    cudaFuncSetAttribute((const void*)gemm_raw<0>,
                         cudaFuncAttributeMaxDynamicSharedMemorySize, GEMM_SMEM);
    cudaFuncSetAttribute((const void*)gemm_raw<1>,
                         cudaFuncAttributeMaxDynamicSharedMemorySize, GEMM_SMEM);
    cudaFuncSetAttribute((const void*)flash_attn3,
                         cudaFuncAttributeMaxDynamicSharedMemorySize, FLASH_SMEM);

    // 0) pre-pass: round hidden; transpose+round both weights to [n][k]
    round_hid_pre<<<N4_HID / 256, 256>>>((const float4*)hidden);
    transpose_pre<0><<<dim3(QKVN / 32, HIDN / 32), dim3(32, 8)>>>(wqkv);
    transpose_pre<1><<<dim3(HIDN / 32, HIDN / 32), dim3(32, 8)>>>(wdense);
    // 1) QKV projection -> g_q/g_k/g_v [B,H,S,D]  (launch #4: ncu target)
    gemm_raw<0><<<32 * 48, 128, GEMM_SMEM>>>(nullptr);
    // 2) xpos rotary on first 32 dims of q,k
    rope_kernel<<<(NB * NH * SEQ * 16) / 256, 256>>>();
    // 3) causal flash attention -> g_ctx
    flash_attn3<<<dim3(SEQ / 128, NH, NB), 256, FLASH_SMEM>>>(amask);
    // 4) output projection -> d_out
    gemm_raw<1><<<32 * 16, 128, GEMM_SMEM>>>(out);
}